// round 3
// baseline (speedup 1.0000x reference)
#include <cuda_runtime.h>
#include <cuda_bf16.h>
#include <math.h>

// Problem constants
static constexpr int kN = 32;
static constexpr int kM = 32;
static constexpr int kP = 196;
static constexpr int kD = 768;
static constexpr float kMargin = 0.5f;
static constexpr float kEps = 1e-8f;

static constexpr int NN_PAIRS = kN * (kN - 1) / 2;   // 496
static constexpr int ND_PAIRS = kN * kM;             // 1024
static constexpr int TOTAL_PAIRS = NN_PAIRS + ND_PAIRS; // 1520

// Tile config for the pair GEMM
static constexpr int TM = 64;   // p-tile
static constexpr int TN = 64;   // q-tile
static constexpr int TK = 16;   // k-chunk
static constexpr int NTILE = (kP + TM - 1) / TM;  // 4 (covers 196 with padding)

// Scratch (device globals — no allocations allowed)
__device__ float g_n1[kN * kP * kD];   // normalized normal embeds
__device__ float g_n2[kM * kP * kD];   // normalized defect embeds
__device__ float g_pair_loss[TOTAL_PAIRS];

// ---------------------------------------------------------------------------
// Kernel 1: row-wise L2 normalize (one block per (image, patch) row)
// ---------------------------------------------------------------------------
__global__ void normalize_kernel(const float* __restrict__ normal,
                                 const float* __restrict__ defect) {
    int row = blockIdx.x;                 // 0 .. 2*N*P-1
    const float* src;
    float* dst;
    if (row < kN * kP) {
        src = normal + (size_t)row * kD;
        dst = g_n1 + (size_t)row * kD;
    } else {
        int r = row - kN * kP;
        src = defect + (size_t)r * kD;
        dst = g_n2 + (size_t)r * kD;
    }

    int t = threadIdx.x;                  // 256 threads, 3 elems each (768)
    float v0 = src[t];
    float v1 = src[t + 256];
    float v2 = src[t + 512];
    float ss = v0 * v0 + v1 * v1 + v2 * v2;

    #pragma unroll
    for (int o = 16; o > 0; o >>= 1) ss += __shfl_xor_sync(0xffffffffu, ss, o);

    __shared__ float ws[8];
    __shared__ float s_scale;
    if ((t & 31) == 0) ws[t >> 5] = ss;
    __syncthreads();
    if (t == 0) {
        float tot = 0.f;
        #pragma unroll
        for (int w = 0; w < 8; w++) tot += ws[w];
        s_scale = 1.0f / (sqrtf(tot) + kEps);
    }
    __syncthreads();
    float s = s_scale;
    dst[t]       = v0 * s;
    dst[t + 256] = v1 * s;
    dst[t + 512] = v2 * s;
}

// ---------------------------------------------------------------------------
// Closed-form decode of linear upper-triangular index (i < j, N=32).
// pairIdx = i*(2N - i - 1)/2 + (j - i - 1)
// ---------------------------------------------------------------------------
__device__ __forceinline__ void decode_tri(int t, int& i, int& j) {
    // i = floor( (2N-1 - sqrt((2N-1)^2 - 8t)) / 2 )
    float disc = (float)((2 * kN - 1) * (2 * kN - 1) - 8 * t);
    int ii = (int)((2.0f * kN - 1.0f - sqrtf(disc)) * 0.5f);
    // guard against fp rounding on the boundary
    while (ii > 0 && t < ii * (2 * kN - ii - 1) / 2) ii--;
    while (t >= (ii + 1) * (2 * kN - ii - 2) / 2 + (ii + 1)) ii++;
    int base = ii * (2 * kN - ii - 1) / 2;
    i = ii;
    j = ii + 1 + (t - base);
}

// ---------------------------------------------------------------------------
// Kernel 2: one block per pair (i,j). Computes
//   m[q] = max_p dot(A[p], B[q])   (A = image i patches, B = image j patches)
// then accumulates the pair's loss contribution into g_pair_loss[pair].
// Tiled SGEMM: 64x64 C-tiles, 256 threads as 16x16, 4x4 accum per thread.
// ---------------------------------------------------------------------------
__global__ void __launch_bounds__(256, 4) pair_kernel() {
    int pairIdx = blockIdx.x;
    const float* A;
    const float* B;
    bool is_nn;
    if (pairIdx < NN_PAIRS) {
        is_nn = true;
        int i, j;
        decode_tri(pairIdx, i, j);
        A = g_n1 + (size_t)i * kP * kD;
        B = g_n1 + (size_t)j * kP * kD;
    } else {
        is_nn = false;
        int t = pairIdx - NN_PAIRS;
        int i = t / kM;
        int j = t % kM;
        A = g_n1 + (size_t)i * kP * kD;
        B = g_n2 + (size_t)j * kP * kD;
    }

    __shared__ float As[TK][TM + 4];   // +4 pad: keeps 16B alignment, cuts STS conflicts
    __shared__ float Bs[TK][TN + 4];
    __shared__ float red[16][TN];
    __shared__ float rbuf[256];

    int tid = threadIdx.x;
    int tx = tid & 15;          // column group (q)
    int ty = tid >> 4;          // row group (p)
    int lm = tid >> 2;          // load row 0..63
    int lk = (tid & 3) * 4;     // load k offset 0,4,8,12

    float block_loss = 0.0f;

    for (int qt = 0; qt < NTILE; qt++) {
        int q0 = qt * TN;
        float colmax[4];
        #pragma unroll
        for (int c = 0; c < 4; c++) colmax[c] = -1e30f;

        for (int pt = 0; pt < NTILE; pt++) {
            int p0 = pt * TM;
            float acc[4][4];
            #pragma unroll
            for (int r = 0; r < 4; r++)
                #pragma unroll
                for (int c = 0; c < 4; c++) acc[r][c] = 0.0f;

            for (int k0 = 0; k0 < kD; k0 += TK) {
                // Stage global -> registers
                float4 av = make_float4(0.f, 0.f, 0.f, 0.f);
                float4 bv = make_float4(0.f, 0.f, 0.f, 0.f);
                int pa = p0 + lm;
                if (pa < kP) av = *(const float4*)(A + (size_t)pa * kD + k0 + lk);
                int qb = q0 + lm;
                if (qb < kP) bv = *(const float4*)(B + (size_t)qb * kD + k0 + lk);

                __syncthreads();   // prior compute reads of As/Bs done
                As[lk + 0][lm] = av.x; As[lk + 1][lm] = av.y;
                As[lk + 2][lm] = av.z; As[lk + 3][lm] = av.w;
                Bs[lk + 0][lm] = bv.x; Bs[lk + 1][lm] = bv.y;
                Bs[lk + 2][lm] = bv.z; Bs[lk + 3][lm] = bv.w;
                __syncthreads();

                #pragma unroll
                for (int kk = 0; kk < TK; kk++) {
                    float4 a4 = *(const float4*)&As[kk][ty * 4];
                    float4 b4 = *(const float4*)&Bs[kk][tx * 4];
                    float ar[4] = {a4.x, a4.y, a4.z, a4.w};
                    float br[4] = {b4.x, b4.y, b4.z, b4.w};
                    #pragma unroll
                    for (int r = 0; r < 4; r++)
                        #pragma unroll
                        for (int c = 0; c < 4; c++)
                            acc[r][c] = fmaf(ar[r], br[c], acc[r][c]);
                }
            }

            // fold this p-tile into the running column max (mask padded p!)
            #pragma unroll
            for (int r = 0; r < 4; r++) {
                int p = p0 + ty * 4 + r;
                if (p < kP) {
                    #pragma unroll
                    for (int c = 0; c < 4; c++)
                        colmax[c] = fmaxf(colmax[c], acc[r][c]);
                }
            }
        }

        // reduce colmax across the 16 ty-groups
        __syncthreads();
        #pragma unroll
        for (int c = 0; c < 4; c++) red[ty][tx * 4 + c] = colmax[c];
        __syncthreads();
        if (tid < TN) {
            float mv = red[0][tid];
            #pragma unroll
            for (int r = 1; r < 16; r++) mv = fmaxf(mv, red[r][tid]);
            int q = q0 + tid;
            if (q < kP) {
                block_loss += is_nn ? (1.0f - mv) : fmaxf(mv - kMargin, 0.0f);
            }
        }
        __syncthreads();
    }

    // block-wide sum of block_loss -> g_pair_loss[pairIdx] (deterministic)
    rbuf[tid] = block_loss;
    __syncthreads();
    #pragma unroll
    for (int s = 128; s > 0; s >>= 1) {
        if (tid < s) rbuf[tid] += rbuf[tid + s];
        __syncthreads();
    }
    if (tid == 0) g_pair_loss[pairIdx] = rbuf[0];
}

// ---------------------------------------------------------------------------
// Kernel 3: deterministic finalize
// ---------------------------------------------------------------------------
__global__ void finalize_kernel(float* __restrict__ out) {
    int t = threadIdx.x;
    float pos = 0.f, neg = 0.f;
    for (int idx = t; idx < TOTAL_PAIRS; idx += 256) {
        float v = g_pair_loss[idx];
        if (idx < NN_PAIRS) pos += v; else neg += v;
    }
    #pragma unroll
    for (int o = 16; o > 0; o >>= 1) {
        pos += __shfl_xor_sync(0xffffffffu, pos, o);
        neg += __shfl_xor_sync(0xffffffffu, neg, o);
    }
    __shared__ float sp[8], sn[8];
    if ((t & 31) == 0) { sp[t >> 5] = pos; sn[t >> 5] = neg; }
    __syncthreads();
    if (t == 0) {
        float ptot = 0.f, ntot = 0.f;
        #pragma unroll
        for (int w = 0; w < 8; w++) { ptot += sp[w]; ntot += sn[w]; }
        out[0] = ptot / (float)(NN_PAIRS * kP) + ntot / (float)(kN * kM * kP);
    }
}

// ---------------------------------------------------------------------------
extern "C" void kernel_launch(void* const* d_in, const int* in_sizes, int n_in,
                              void* d_out, int out_size) {
    const float* normal = (const float*)d_in[0];
    const float* defect = (const float*)d_in[1];
    float* out = (float*)d_out;

    normalize_kernel<<<(kN + kM) * kP, 256>>>(normal, defect);
    pair_kernel<<<TOTAL_PAIRS, 256>>>();
    finalize_kernel<<<1, 256>>>(out);
}

// round 5
// speedup vs baseline: 5.2922x; 5.2922x over previous
#include <cuda_runtime.h>
#include <cuda_bf16.h>
#include <math.h>
#include <stdint.h>

// ---------------------------------------------------------------------------
// Problem constants
// ---------------------------------------------------------------------------
static constexpr int kN = 32;
static constexpr int kM = 32;
static constexpr int kP = 196;
static constexpr int kD = 768;
static constexpr float kMargin = 0.5f;
static constexpr float kEps = 1e-8f;

static constexpr int NN_PAIRS = kN * (kN - 1) / 2;      // 496
static constexpr int ND_PAIRS = kN * kM;                // 1024
static constexpr int TOTAL_PAIRS = NN_PAIRS + ND_PAIRS; // 1520

static constexpr int KC = 32;            // k-chunk in bf16 halves
static constexpr int NCHUNK = kD / KC;   // 24
static constexpr int STRIDE = 40;        // smem row stride in halves (80B: conflict-free ldmatrix)

// Scratch (device globals — no allocations). 16B-aligned for uint4 access.
__device__ __align__(16) __nv_bfloat16 g_n1b[kN * kP * kD];
__device__ __align__(16) __nv_bfloat16 g_n2b[kM * kP * kD];
__device__ float g_pair_loss[TOTAL_PAIRS];

// ---------------------------------------------------------------------------
__device__ __forceinline__ uint32_t smem_u32(const void* p) {
    uint32_t a;
    asm("{ .reg .u64 t; cvta.to.shared.u64 t, %1; cvt.u32.u64 %0, t; }" : "=r"(a) : "l"(p));
    return a;
}

__device__ __forceinline__ void ldmatrix_x4(uint32_t& r0, uint32_t& r1,
                                            uint32_t& r2, uint32_t& r3, uint32_t addr) {
    asm volatile("ldmatrix.sync.aligned.m8n8.x4.shared.b16 {%0,%1,%2,%3}, [%4];"
                 : "=r"(r0), "=r"(r1), "=r"(r2), "=r"(r3) : "r"(addr));
}

__device__ __forceinline__ void mma_bf16(float* d, const uint32_t* a, uint32_t b0, uint32_t b1) {
    asm volatile(
        "mma.sync.aligned.m16n8k16.row.col.f32.bf16.bf16.f32 "
        "{%0,%1,%2,%3}, {%4,%5,%6,%7}, {%8,%9}, {%0,%1,%2,%3};"
        : "+f"(d[0]), "+f"(d[1]), "+f"(d[2]), "+f"(d[3])
        : "r"(a[0]), "r"(a[1]), "r"(a[2]), "r"(a[3]), "r"(b0), "r"(b1));
}

// ---------------------------------------------------------------------------
// Kernel 1: row-wise L2 normalize, fp32 -> bf16
// ---------------------------------------------------------------------------
__global__ void normalize_kernel(const float* __restrict__ normal,
                                 const float* __restrict__ defect) {
    int row = blockIdx.x;
    const float* src;
    __nv_bfloat16* dst;
    if (row < kN * kP) {
        src = normal + (size_t)row * kD;
        dst = g_n1b + (size_t)row * kD;
    } else {
        int r = row - kN * kP;
        src = defect + (size_t)r * kD;
        dst = g_n2b + (size_t)r * kD;
    }
    int t = threadIdx.x;
    float v0 = src[t], v1 = src[t + 256], v2 = src[t + 512];
    float ss = v0 * v0 + v1 * v1 + v2 * v2;
    #pragma unroll
    for (int o = 16; o > 0; o >>= 1) ss += __shfl_xor_sync(0xffffffffu, ss, o);
    __shared__ float ws[8];
    __shared__ float s_scale;
    if ((t & 31) == 0) ws[t >> 5] = ss;
    __syncthreads();
    if (t == 0) {
        float tot = 0.f;
        #pragma unroll
        for (int w = 0; w < 8; w++) tot += ws[w];
        s_scale = 1.0f / (sqrtf(tot) + kEps);
    }
    __syncthreads();
    float s = s_scale;
    dst[t]       = __float2bfloat16(v0 * s);
    dst[t + 256] = __float2bfloat16(v1 * s);
    dst[t + 512] = __float2bfloat16(v2 * s);
}

// ---------------------------------------------------------------------------
__device__ __forceinline__ void decode_tri(int t, int& i, int& j) {
    float disc = (float)((2 * kN - 1) * (2 * kN - 1) - 8 * t);
    int ii = (int)((2.0f * kN - 1.0f - sqrtf(disc)) * 0.5f);
    while (ii > 0 && t < ii * (2 * kN - ii - 1) / 2) ii--;
    while (t >= (ii + 1) * (2 * kN - ii - 2) / 2 + (ii + 1)) ii++;
    int base = ii * (2 * kN - ii - 1) / 2;
    i = ii;
    j = ii + 1 + (t - base);
}

// ---------------------------------------------------------------------------
// Kernel 2: one CTA per pair. bf16 mma.sync GEMM + fused column-max + loss.
// C blocks 128x128, warp grid 4(M) x 2(N), warp tile 32x64 (2x8 m16n8 frags).
// ---------------------------------------------------------------------------
__global__ void __launch_bounds__(256, 2) pair_kernel() {
    __shared__ __align__(16) __nv_bfloat16 As[2][128 * STRIDE];
    __shared__ __align__(16) __nv_bfloat16 Bs[2][128 * STRIDE];
    __shared__ float s_part[4][128];
    __shared__ float s_colmax[256];
    __shared__ float s_rbuf[256];

    int tid = threadIdx.x;
    int lane = tid & 31;
    int wid = tid >> 5;
    int wy = wid >> 1;   // 0..3 -> M sub-block
    int wx = wid & 1;    // 0..1 -> N sub-block

    // Pair decode
    int pairIdx = blockIdx.x;
    const __nv_bfloat16* A;
    const __nv_bfloat16* B;
    bool is_nn;
    if (pairIdx < NN_PAIRS) {
        is_nn = true;
        int i, j;
        decode_tri(pairIdx, i, j);
        A = g_n1b + (size_t)i * kP * kD;
        B = g_n1b + (size_t)j * kP * kD;
    } else {
        is_nn = false;
        int t = pairIdx - NN_PAIRS;
        A = g_n1b + (size_t)(t / kM) * kP * kD;
        B = g_n2b + (size_t)(t % kM) * kP * kD;
    }

    s_colmax[tid] = -1e30f;
    __syncthreads();

    // Gmem staging indices: 512 uint4 per matrix per chunk, 2 per thread
    int ldRow0 = tid >> 2;              // 0..63
    int ldRow1 = ldRow0 + 64;           // 64..127
    int ldSeg  = (tid & 3) * 8;         // halves offset within 32-half window

    // ldmatrix lane addressing (byte offsets within a staging buffer)
    int ar = lane & 15, ah = lane >> 4;
    uint32_t aOffB = (uint32_t)(((wy * 32 + ar) * STRIDE + ah * 8) * 2);
    int bq = lane >> 3, brr = lane & 7;
    uint32_t bOffB = (uint32_t)(((wx * 64 + ((bq >> 1) & 1) * 8 + brr) * STRIDE + (bq & 1) * 8) * 2);

    const uint4 z4 = make_uint4(0u, 0u, 0u, 0u);

    #pragma unroll 1
    for (int mb = 0; mb < 2; mb++) {
        int am0 = mb * 128;
        #pragma unroll 1
        for (int nb = 0; nb < 2; nb++) {
            int bn0 = nb * 128;

            float acc[2][8][4];
            #pragma unroll
            for (int mt = 0; mt < 2; mt++)
                #pragma unroll
                for (int nt = 0; nt < 8; nt++)
                    #pragma unroll
                    for (int e = 0; e < 4; e++) acc[mt][nt][e] = 0.0f;

            // Preload chunk 0
            uint4 ra0, ra1, rb0, rb1;
            {
                int r0 = am0 + ldRow0, r1 = am0 + ldRow1;
                ra0 = (r0 < kP) ? *(const uint4*)(A + (size_t)r0 * kD + ldSeg) : z4;
                ra1 = (r1 < kP) ? *(const uint4*)(A + (size_t)r1 * kD + ldSeg) : z4;
                int s0 = bn0 + ldRow0, s1 = bn0 + ldRow1;
                rb0 = (s0 < kP) ? *(const uint4*)(B + (size_t)s0 * kD + ldSeg) : z4;
                rb1 = (s1 < kP) ? *(const uint4*)(B + (size_t)s1 * kD + ldSeg) : z4;
            }
            *(uint4*)(&As[0][ldRow0 * STRIDE + ldSeg]) = ra0;
            *(uint4*)(&As[0][ldRow1 * STRIDE + ldSeg]) = ra1;
            *(uint4*)(&Bs[0][ldRow0 * STRIDE + ldSeg]) = rb0;
            *(uint4*)(&Bs[0][ldRow1 * STRIDE + ldSeg]) = rb1;
            __syncthreads();

            #pragma unroll 1
            for (int c = 0; c < NCHUNK; c++) {
                int b = c & 1;
                // Issue next chunk's global loads early (hide L2 latency behind mma)
                if (c + 1 < NCHUNK) {
                    int k0 = (c + 1) * KC + ldSeg;
                    int r0 = am0 + ldRow0, r1 = am0 + ldRow1;
                    ra0 = (r0 < kP) ? *(const uint4*)(A + (size_t)r0 * kD + k0) : z4;
                    ra1 = (r1 < kP) ? *(const uint4*)(A + (size_t)r1 * kD + k0) : z4;
                    int s0 = bn0 + ldRow0, s1 = bn0 + ldRow1;
                    rb0 = (s0 < kP) ? *(const uint4*)(B + (size_t)s0 * kD + k0) : z4;
                    rb1 = (s1 < kP) ? *(const uint4*)(B + (size_t)s1 * kD + k0) : z4;
                }

                uint32_t smA = smem_u32(&As[b][0]);
                uint32_t smB = smem_u32(&Bs[b][0]);
                #pragma unroll
                for (int ks = 0; ks < 2; ks++) {
                    uint32_t a0[2][4];
                    #pragma unroll
                    for (int mt = 0; mt < 2; mt++)
                        ldmatrix_x4(a0[mt][0], a0[mt][1], a0[mt][2], a0[mt][3],
                                    smA + aOffB + (uint32_t)((mt * 16 * STRIDE + ks * 16) * 2));
                    #pragma unroll
                    for (int ntp = 0; ntp < 4; ntp++) {
                        uint32_t b0, b1, b2, b3;
                        ldmatrix_x4(b0, b1, b2, b3,
                                    smB + bOffB + (uint32_t)((ntp * 16 * STRIDE + ks * 16) * 2));
                        #pragma unroll
                        for (int mt = 0; mt < 2; mt++) {
                            mma_bf16(acc[mt][ntp * 2 + 0], a0[mt], b0, b1);
                            mma_bf16(acc[mt][ntp * 2 + 1], a0[mt], b2, b3);
                        }
                    }
                }

                // Store next chunk into the other buffer (safe: distinct buffer)
                if (c + 1 < NCHUNK) {
                    int nbuf = (c + 1) & 1;
                    *(uint4*)(&As[nbuf][ldRow0 * STRIDE + ldSeg]) = ra0;
                    *(uint4*)(&As[nbuf][ldRow1 * STRIDE + ldSeg]) = ra1;
                    *(uint4*)(&Bs[nbuf][ldRow0 * STRIDE + ldSeg]) = rb0;
                    *(uint4*)(&Bs[nbuf][ldRow1 * STRIDE + ldSeg]) = rb1;
                }
                __syncthreads();
            }

            // ----- Epilogue: column max over this block's valid rows -----
            int rbase = am0 + wy * 32 + (lane >> 2);
            #pragma unroll
            for (int nt = 0; nt < 8; nt++) {
                float c0 = -1e30f, c1 = -1e30f;
                #pragma unroll
                for (int mt = 0; mt < 2; mt++) {
                    int r1 = rbase + mt * 16;
                    bool v1 = r1 < kP, v2 = (r1 + 8) < kP;
                    const float* cc = acc[mt][nt];
                    c0 = fmaxf(c0, fmaxf(v1 ? cc[0] : -1e30f, v2 ? cc[2] : -1e30f));
                    c1 = fmaxf(c1, fmaxf(v1 ? cc[1] : -1e30f, v2 ? cc[3] : -1e30f));
                }
                #pragma unroll
                for (int o = 4; o <= 16; o <<= 1) {
                    c0 = fmaxf(c0, __shfl_xor_sync(0xffffffffu, c0, o));
                    c1 = fmaxf(c1, __shfl_xor_sync(0xffffffffu, c1, o));
                }
                if (lane < 4) {
                    int col = wx * 64 + nt * 8 + 2 * lane;
                    s_part[wy][col]     = c0;
                    s_part[wy][col + 1] = c1;
                }
            }
            __syncthreads();
            if (tid < 128) {
                float m = fmaxf(fmaxf(s_part[0][tid], s_part[1][tid]),
                                fmaxf(s_part[2][tid], s_part[3][tid]));
                s_colmax[bn0 + tid] = fmaxf(s_colmax[bn0 + tid], m);
            }
            __syncthreads();
        }
    }

    // ----- Loss over q < 196, block reduce -----
    float v = 0.0f;
    if (tid < kP) {
        float m = s_colmax[tid];
        v = is_nn ? (1.0f - m) : fmaxf(m - kMargin, 0.0f);
    }
    s_rbuf[tid] = v;
    __syncthreads();
    #pragma unroll
    for (int s = 128; s > 0; s >>= 1) {
        if (tid < s) s_rbuf[tid] += s_rbuf[tid + s];
        __syncthreads();
    }
    if (tid == 0) g_pair_loss[pairIdx] = s_rbuf[0];
}

// ---------------------------------------------------------------------------
// Kernel 3: deterministic finalize
// ---------------------------------------------------------------------------
__global__ void finalize_kernel(float* __restrict__ out) {
    int t = threadIdx.x;
    float pos = 0.f, neg = 0.f;
    for (int idx = t; idx < TOTAL_PAIRS; idx += 256) {
        float v = g_pair_loss[idx];
        if (idx < NN_PAIRS) pos += v; else neg += v;
    }
    #pragma unroll
    for (int o = 16; o > 0; o >>= 1) {
        pos += __shfl_xor_sync(0xffffffffu, pos, o);
        neg += __shfl_xor_sync(0xffffffffu, neg, o);
    }
    __shared__ float sp[8], sn[8];
    if ((t & 31) == 0) { sp[t >> 5] = pos; sn[t >> 5] = neg; }
    __syncthreads();
    if (t == 0) {
        float ptot = 0.f, ntot = 0.f;
        #pragma unroll
        for (int w = 0; w < 8; w++) { ptot += sp[w]; ntot += sn[w]; }
        out[0] = ptot / (float)(NN_PAIRS * kP) + ntot / (float)(kN * kM * kP);
    }
}

// ---------------------------------------------------------------------------
extern "C" void kernel_launch(void* const* d_in, const int* in_sizes, int n_in,
                              void* d_out, int out_size) {
    const float* normal = (const float*)d_in[0];
    const float* defect = (const float*)d_in[1];
    float* out = (float*)d_out;

    normalize_kernel<<<(kN + kM) * kP, 256>>>(normal, defect);
    pair_kernel<<<TOTAL_PAIRS, 256>>>();
    finalize_kernel<<<1, 256>>>(out);
}

// round 8
// speedup vs baseline: 8.0458x; 1.5203x over previous
#include <cuda_runtime.h>
#include <cuda_bf16.h>
#include <math.h>
#include <stdint.h>

// ---------------------------------------------------------------------------
// Problem constants
// ---------------------------------------------------------------------------
static constexpr int kN = 32;
static constexpr int kM = 32;
static constexpr int kP = 196;
static constexpr int kD = 768;
static constexpr float kMargin = 0.5f;
static constexpr float kEps = 1e-8f;

static constexpr int NN_PAIRS = kN * (kN - 1) / 2;      // 496
static constexpr int ND_PAIRS = kN * kM;                // 1024
static constexpr int TOTAL_PAIRS = NN_PAIRS + ND_PAIRS; // 1520

static constexpr int KC = 32;            // k-chunk in bf16 halves
static constexpr int NCHUNK = kD / KC;   // 24
static constexpr int STRIDE = 40;        // smem row stride in halves (80B: conflict-free ldmatrix)

// Scratch (device globals — no allocations). 16B-aligned for vector access.
__device__ __align__(16) __nv_bfloat16 g_n1b[kN * kP * kD];
__device__ __align__(16) __nv_bfloat16 g_n2b[kM * kP * kD];
__device__ float g_pair_loss[TOTAL_PAIRS];

// ---------------------------------------------------------------------------
__device__ __forceinline__ uint32_t smem_u32(const void* p) {
    uint32_t a;
    asm("{ .reg .u64 t; cvta.to.shared.u64 t, %1; cvt.u32.u64 %0, t; }" : "=r"(a) : "l"(p));
    return a;
}

__device__ __forceinline__ void ldmatrix_x4(uint32_t& r0, uint32_t& r1,
                                            uint32_t& r2, uint32_t& r3, uint32_t addr) {
    asm volatile("ldmatrix.sync.aligned.m8n8.x4.shared.b16 {%0,%1,%2,%3}, [%4];"
                 : "=r"(r0), "=r"(r1), "=r"(r2), "=r"(r3) : "r"(addr));
}

__device__ __forceinline__ void mma_bf16(float* d, const uint32_t* a, uint32_t b0, uint32_t b1) {
    asm volatile(
        "mma.sync.aligned.m16n8k16.row.col.f32.bf16.bf16.f32 "
        "{%0,%1,%2,%3}, {%4,%5,%6,%7}, {%8,%9}, {%0,%1,%2,%3};"
        : "+f"(d[0]), "+f"(d[1]), "+f"(d[2]), "+f"(d[3])
        : "r"(a[0]), "r"(a[1]), "r"(a[2]), "r"(a[3]), "r"(b0), "r"(b1));
}

// cp.async 16B with zero-fill when invalid (src-size form)
__device__ __forceinline__ void cpa16(uint32_t dst, const void* src, bool valid) {
    int sz = valid ? 16 : 0;
    asm volatile("cp.async.cg.shared.global [%0], [%1], 16, %2;"
                 :: "r"(dst), "l"(src), "r"(sz) : "memory");
}
#define CPA_COMMIT() asm volatile("cp.async.commit_group;" ::: "memory")
#define CPA_WAIT0()  asm volatile("cp.async.wait_group 0;" ::: "memory")

// ---------------------------------------------------------------------------
// Kernel 1: row-wise L2 normalize, fp32 -> bf16
// ---------------------------------------------------------------------------
__global__ void normalize_kernel(const float* __restrict__ normal,
                                 const float* __restrict__ defect) {
    int row = blockIdx.x;
    const float* src;
    __nv_bfloat16* dst;
    if (row < kN * kP) {
        src = normal + (size_t)row * kD;
        dst = g_n1b + (size_t)row * kD;
    } else {
        int r = row - kN * kP;
        src = defect + (size_t)r * kD;
        dst = g_n2b + (size_t)r * kD;
    }
    int t = threadIdx.x;
    float v0 = src[t], v1 = src[t + 256], v2 = src[t + 512];
    float ss = v0 * v0 + v1 * v1 + v2 * v2;
    #pragma unroll
    for (int o = 16; o > 0; o >>= 1) ss += __shfl_xor_sync(0xffffffffu, ss, o);
    __shared__ float ws[8];
    __shared__ float s_scale;
    if ((t & 31) == 0) ws[t >> 5] = ss;
    __syncthreads();
    if (t == 0) {
        float tot = 0.f;
        #pragma unroll
        for (int w = 0; w < 8; w++) tot += ws[w];
        s_scale = 1.0f / (sqrtf(tot) + kEps);
    }
    __syncthreads();
    float s = s_scale;
    dst[t]       = __float2bfloat16(v0 * s);
    dst[t + 256] = __float2bfloat16(v1 * s);
    dst[t + 512] = __float2bfloat16(v2 * s);
}

// ---------------------------------------------------------------------------
__device__ __forceinline__ void decode_tri(int t, int& i, int& j) {
    float disc = (float)((2 * kN - 1) * (2 * kN - 1) - 8 * t);
    int ii = (int)((2.0f * kN - 1.0f - sqrtf(disc)) * 0.5f);
    while (ii > 0 && t < ii * (2 * kN - ii - 1) / 2) ii--;
    while (t >= (ii + 1) * (2 * kN - ii - 2) / 2 + (ii + 1)) ii++;
    int base = ii * (2 * kN - ii - 1) / 2;
    i = ii;
    j = ii + 1 + (t - base);
}

// ---------------------------------------------------------------------------
// Kernel 2: one CTA per pair. bf16 mma.sync GEMM + fused column-max + loss.
// C blocks 128x128 (2x2 over the padded 256 range); warp grid 4(M) x 2(N),
// warp tile 32x64. Fully-padded warp tiles / nt-tiles are skipped.
// ---------------------------------------------------------------------------
__global__ void __launch_bounds__(256, 2) pair_kernel() {
    __shared__ __align__(16) __nv_bfloat16 As[2][128 * STRIDE];
    __shared__ __align__(16) __nv_bfloat16 Bs[2][128 * STRIDE];
    __shared__ float s_part[4][128];
    __shared__ float s_colmax[256];
    __shared__ float s_rbuf[256];

    int tid = threadIdx.x;
    int lane = tid & 31;
    int wid = tid >> 5;
    int wy = wid >> 1;   // 0..3 -> M sub-block
    int wx = wid & 1;    // 0..1 -> N sub-block

    // Pair decode
    int pairIdx = blockIdx.x;
    const __nv_bfloat16* A;
    const __nv_bfloat16* B;
    bool is_nn;
    if (pairIdx < NN_PAIRS) {
        is_nn = true;
        int i, j;
        decode_tri(pairIdx, i, j);
        A = g_n1b + (size_t)i * kP * kD;
        B = g_n1b + (size_t)j * kP * kD;
    } else {
        is_nn = false;
        int t = pairIdx - NN_PAIRS;
        A = g_n1b + (size_t)(t / kM) * kP * kD;
        B = g_n2b + (size_t)(t % kM) * kP * kD;
    }

    s_colmax[tid] = -1e30f;
    __syncthreads();

    // Staging indices: each thread cp.asyncs 2 A rows + 2 B rows x 16B per chunk
    int ldRow0 = tid >> 2;              // 0..63
    int ldRow1 = ldRow0 + 64;           // 64..127
    int ldSeg  = (tid & 3) * 8;         // halves offset within 32-half window

    uint32_t smA[2] = { smem_u32(&As[0][0]), smem_u32(&As[1][0]) };
    uint32_t smB[2] = { smem_u32(&Bs[0][0]), smem_u32(&Bs[1][0]) };
    uint32_t dA0 = (uint32_t)((ldRow0 * STRIDE + ldSeg) * 2);
    uint32_t dA1 = (uint32_t)((ldRow1 * STRIDE + ldSeg) * 2);

    // ldmatrix lane addressing (byte offsets within a staging buffer)
    int ar = lane & 15, ah = lane >> 4;
    uint32_t aOffB = (uint32_t)(((wy * 32 + ar) * STRIDE + ah * 8) * 2);
    int bq = lane >> 3, brr = lane & 7;
    uint32_t bOffB = (uint32_t)(((wx * 64 + ((bq >> 1) & 1) * 8 + brr) * STRIDE + (bq & 1) * 8) * 2);

    #pragma unroll 1
    for (int mb = 0; mb < 2; mb++) {
        int am0 = mb * 128;
        int mRows = mb ? (kP - 128) : 128;              // 68 or 128
        bool warpM = (wy * 32) < mRows;                 // mb=1: wy==3 idle
        #pragma unroll 1
        for (int nb = 0; nb < 2; nb++) {
            int bn0 = nb * 128;
            int nCols = nb ? (kP - 128) : 128;          // 68 or 128

            float acc[2][8][4];
            #pragma unroll
            for (int mt = 0; mt < 2; mt++)
                #pragma unroll
                for (int nt = 0; nt < 8; nt++)
                    #pragma unroll
                    for (int e = 0; e < 4; e++) acc[mt][nt][e] = 0.0f;

            // Preload chunk 0 into buffer 0
            {
                int r0 = am0 + ldRow0, r1 = am0 + ldRow1;
                int s0 = bn0 + ldRow0, s1 = bn0 + ldRow1;
                cpa16(smA[0] + dA0, A + (size_t)r0 * kD + ldSeg, r0 < kP);
                cpa16(smA[0] + dA1, A + (size_t)r1 * kD + ldSeg, r1 < kP);
                cpa16(smB[0] + dA0, B + (size_t)s0 * kD + ldSeg, s0 < kP);
                cpa16(smB[0] + dA1, B + (size_t)s1 * kD + ldSeg, s1 < kP);
                CPA_COMMIT();
            }

            #pragma unroll 1
            for (int c = 0; c < NCHUNK; c++) {
                int b = c & 1;
                CPA_WAIT0();
                __syncthreads();   // buf c ready; all warps past mma(c-1)

                if (c + 1 < NCHUNK) {
                    int nbuf = (c + 1) & 1;
                    int k0 = (c + 1) * KC + ldSeg;
                    int r0 = am0 + ldRow0, r1 = am0 + ldRow1;
                    int s0 = bn0 + ldRow0, s1 = bn0 + ldRow1;
                    cpa16(smA[nbuf] + dA0, A + (size_t)r0 * kD + k0, r0 < kP);
                    cpa16(smA[nbuf] + dA1, A + (size_t)r1 * kD + k0, r1 < kP);
                    cpa16(smB[nbuf] + dA0, B + (size_t)s0 * kD + k0, s0 < kP);
                    cpa16(smB[nbuf] + dA1, B + (size_t)s1 * kD + k0, s1 < kP);
                    CPA_COMMIT();
                }

                if (warpM) {
                    #pragma unroll
                    for (int ks = 0; ks < 2; ks++) {
                        uint32_t a0[2][4];
                        #pragma unroll
                        for (int mt = 0; mt < 2; mt++)
                            ldmatrix_x4(a0[mt][0], a0[mt][1], a0[mt][2], a0[mt][3],
                                        smA[b] + aOffB + (uint32_t)((mt * 16 * STRIDE + ks * 16) * 2));
                        #pragma unroll
                        for (int ntp = 0; ntp < 4; ntp++) {
                            if (wx * 64 + ntp * 16 < nCols) {
                                uint32_t b0, b1, b2, b3;
                                ldmatrix_x4(b0, b1, b2, b3,
                                            smB[b] + bOffB + (uint32_t)((ntp * 16 * STRIDE + ks * 16) * 2));
                                #pragma unroll
                                for (int mt = 0; mt < 2; mt++) {
                                    mma_bf16(acc[mt][ntp * 2 + 0], a0[mt], b0, b1);
                                    mma_bf16(acc[mt][ntp * 2 + 1], a0[mt], b2, b3);
                                }
                            }
                        }
                    }
                }
            }
            __syncthreads();   // all mma done before s_part reuse

            // ----- Epilogue: column max over this block's valid rows -----
            int rbase = am0 + wy * 32 + (lane >> 2);
            #pragma unroll
            for (int nt = 0; nt < 8; nt++) {
                float c0 = -1e30f, c1 = -1e30f;
                #pragma unroll
                for (int mt = 0; mt < 2; mt++) {
                    int r1 = rbase + mt * 16;
                    bool v1 = r1 < kP, v2 = (r1 + 8) < kP;
                    const float* cc = acc[mt][nt];
                    c0 = fmaxf(c0, fmaxf(v1 ? cc[0] : -1e30f, v2 ? cc[2] : -1e30f));
                    c1 = fmaxf(c1, fmaxf(v1 ? cc[1] : -1e30f, v2 ? cc[3] : -1e30f));
                }
                #pragma unroll
                for (int o = 4; o <= 16; o <<= 1) {
                    c0 = fmaxf(c0, __shfl_xor_sync(0xffffffffu, c0, o));
                    c1 = fmaxf(c1, __shfl_xor_sync(0xffffffffu, c1, o));
                }
                if (lane < 4) {
                    int col = wx * 64 + nt * 8 + 2 * lane;
                    s_part[wy][col]     = c0;
                    s_part[wy][col + 1] = c1;
                }
            }
            __syncthreads();
            if (tid < 128) {
                float m = fmaxf(fmaxf(s_part[0][tid], s_part[1][tid]),
                                fmaxf(s_part[2][tid], s_part[3][tid]));
                s_colmax[bn0 + tid] = fmaxf(s_colmax[bn0 + tid], m);
            }
            __syncthreads();
        }
    }

    // ----- Loss over q < 196, block reduce -----
    float v = 0.0f;
    if (tid < kP) {
        float m = s_colmax[tid];
        v = is_nn ? (1.0f - m) : fmaxf(m - kMargin, 0.0f);
    }
    s_rbuf[tid] = v;
    __syncthreads();
    #pragma unroll
    for (int s = 128; s > 0; s >>= 1) {
        if (tid < s) s_rbuf[tid] += s_rbuf[tid + s];
        __syncthreads();
    }
    if (tid == 0) g_pair_loss[pairIdx] = s_rbuf[0];
}

// ---------------------------------------------------------------------------
// Kernel 3: deterministic finalize
// ---------------------------------------------------------------------------
__global__ void finalize_kernel(float* __restrict__ out) {
    int t = threadIdx.x;
    float pos = 0.f, neg = 0.f;
    for (int idx = t; idx < TOTAL_PAIRS; idx += 256) {
        float v = g_pair_loss[idx];
        if (idx < NN_PAIRS) pos += v; else neg += v;
    }
    #pragma unroll
    for (int o = 16; o > 0; o >>= 1) {
        pos += __shfl_xor_sync(0xffffffffu, pos, o);
        neg += __shfl_xor_sync(0xffffffffu, neg, o);
    }
    __shared__ float sp[8], sn[8];
    if ((t & 31) == 0) { sp[t >> 5] = pos; sn[t >> 5] = neg; }
    __syncthreads();
    if (t == 0) {
        float ptot = 0.f, ntot = 0.f;
        #pragma unroll
        for (int w = 0; w < 8; w++) { ptot += sp[w]; ntot += sn[w]; }
        out[0] = ptot / (float)(NN_PAIRS * kP) + ntot / (float)(kN * kM * kP);
    }
}

// ---------------------------------------------------------------------------
extern "C" void kernel_launch(void* const* d_in, const int* in_sizes, int n_in,
                              void* d_out, int out_size) {
    const float* normal = (const float*)d_in[0];
    const float* defect = (const float*)d_in[1];
    float* out = (float*)d_out;

    normalize_kernel<<<(kN + kM) * kP, 256>>>(normal, defect);
    pair_kernel<<<TOTAL_PAIRS, 256>>>();
    finalize_kernel<<<1, 256>>>(out);
}